// round 4
// baseline (speedup 1.0000x reference)
#include <cuda_runtime.h>

// Scratch for per-block partial sums (allocation-free per harness rules).
// Fully overwritten by kernel 1 every launch, fully consumed by kernel 2,
// so no zeroing needed and graph replays are deterministic.
#define MAX_BLOCKS 4096
__device__ float g_partials[MAX_BLOCKS];

// Kernel 1: streaming distance + block reduction.
// Each float4 of preds/targets holds TWO complete (x,y) points.
__global__ void dist_partial_kernel(const float4* __restrict__ p,
                                    const float4* __restrict__ t,
                                    int n4, int n_elems) {
    float acc = 0.0f;
    const int stride = gridDim.x * blockDim.x;
    for (int i = blockIdx.x * blockDim.x + threadIdx.x; i < n4; i += stride) {
        float4 a = __ldcs(&p[i]);
        float4 b = __ldcs(&t[i]);
        float dx0 = a.x - b.x, dy0 = a.y - b.y;
        float dx1 = a.z - b.z, dy1 = a.w - b.w;
        acc += sqrtf(fmaf(dx0, dx0, dy0 * dy0));
        acc += sqrtf(fmaf(dx1, dx1, dy1 * dy1));
    }

    // Tail: if total float count isn't a multiple of 4, there is exactly one
    // leftover point (2 floats). Handle it once, in a fixed thread.
    if (blockIdx.x == 0 && threadIdx.x == 0 && (n_elems & 3)) {
        const float* pf = (const float*)p;
        const float* tf = (const float*)t;
        int base = n4 * 4;
        float dx = pf[base] - tf[base];
        float dy = pf[base + 1] - tf[base + 1];
        acc += sqrtf(fmaf(dx, dx, dy * dy));
    }

    // Warp reduce
    #pragma unroll
    for (int o = 16; o > 0; o >>= 1)
        acc += __shfl_down_sync(0xFFFFFFFFu, acc, o);

    __shared__ float s[32];
    if ((threadIdx.x & 31) == 0) s[threadIdx.x >> 5] = acc;
    __syncthreads();

    if (threadIdx.x < 32) {
        float v = (threadIdx.x < (blockDim.x >> 5)) ? s[threadIdx.x] : 0.0f;
        #pragma unroll
        for (int o = 16; o > 0; o >>= 1)
            v += __shfl_down_sync(0xFFFFFFFFu, v, o);
        if (threadIdx.x == 0) g_partials[blockIdx.x] = v;
    }
}

// Kernel 2: deterministic final reduction + scale by 1/(N+1).
__global__ void dist_final_kernel(float* __restrict__ out, int nblocks, float inv_np1) {
    float acc = 0.0f;
    for (int i = threadIdx.x; i < nblocks; i += blockDim.x)
        acc += g_partials[i];

    #pragma unroll
    for (int o = 16; o > 0; o >>= 1)
        acc += __shfl_down_sync(0xFFFFFFFFu, acc, o);

    __shared__ float s[32];
    if ((threadIdx.x & 31) == 0) s[threadIdx.x >> 5] = acc;
    __syncthreads();

    if (threadIdx.x < 32) {
        float v = (threadIdx.x < (blockDim.x >> 5)) ? s[threadIdx.x] : 0.0f;
        #pragma unroll
        for (int o = 16; o > 0; o >>= 1)
            v += __shfl_down_sync(0xFFFFFFFFu, v, o);
        if (threadIdx.x == 0) out[0] = v * inv_np1;
    }
}

extern "C" void kernel_launch(void* const* d_in, const int* in_sizes, int n_in,
                              void* d_out, int out_size) {
    const float4* preds   = (const float4*)d_in[0];
    const float4* targets = (const float4*)d_in[1];
    float* out = (float*)d_out;

    const int n_elems = in_sizes[0];          // N*2 floats
    const int n4      = n_elems >> 2;         // float4 count (2 points each)
    const long long n_points = (long long)n_elems / 2;

    const int THREADS = 256;
    const int BLOCKS  = 1184;                 // 148 SMs * 8 CTAs -> one full wave

    float inv_np1 = 1.0f / (float)(n_points + 1);

    dist_partial_kernel<<<BLOCKS, THREADS>>>(preds, targets, n4, n_elems);
    dist_final_kernel<<<1, 256>>>(out, BLOCKS, inv_np1);
}

// round 5
// speedup vs baseline: 1.0126x; 1.0126x over previous
#include <cuda_runtime.h>

// Allocation-free scratch (harness forbids cudaMalloc anywhere).
#define MAX_BLOCKS 4096
__device__ float        g_partials[MAX_BLOCKS];
__device__ unsigned int g_count = 0;   // reset by the last block each launch -> replay-safe

// Single fused kernel: streaming distance, per-block reduction, and a
// last-block-done final reduction (deterministic fixed-order sum, no float
// atomics), so there is no second launch.
__global__ void dist_fused_kernel(const float4* __restrict__ p,
                                  const float4* __restrict__ t,
                                  int n4, int n_elems, float inv_np1,
                                  float* __restrict__ out) {
    float acc = 0.0f;
    const int stride = gridDim.x * blockDim.x;
    for (int i = blockIdx.x * blockDim.x + threadIdx.x; i < n4; i += stride) {
        float4 a = __ldcs(&p[i]);
        float4 b = __ldcs(&t[i]);
        float dx0 = a.x - b.x, dy0 = a.y - b.y;
        float dx1 = a.z - b.z, dy1 = a.w - b.w;
        acc += sqrtf(fmaf(dx0, dx0, dy0 * dy0));
        acc += sqrtf(fmaf(dx1, dx1, dy1 * dy1));
    }

    // Tail: one leftover (x,y) point if float count isn't a multiple of 4.
    if (blockIdx.x == 0 && threadIdx.x == 0 && (n_elems & 3)) {
        const float* pf = (const float*)p;
        const float* tf = (const float*)t;
        int base = n4 * 4;
        float dx = pf[base] - tf[base];
        float dy = pf[base + 1] - tf[base + 1];
        acc += sqrtf(fmaf(dx, dx, dy * dy));
    }

    // ---- block reduction ----
    #pragma unroll
    for (int o = 16; o > 0; o >>= 1)
        acc += __shfl_down_sync(0xFFFFFFFFu, acc, o);

    __shared__ float s[32];
    if ((threadIdx.x & 31) == 0) s[threadIdx.x >> 5] = acc;
    __syncthreads();

    float blocksum = 0.0f;
    if (threadIdx.x < 32) {
        float v = (threadIdx.x < (blockDim.x >> 5)) ? s[threadIdx.x] : 0.0f;
        #pragma unroll
        for (int o = 16; o > 0; o >>= 1)
            v += __shfl_down_sync(0xFFFFFFFFu, v, o);
        blocksum = v;
    }

    // ---- last-block-done final reduction ----
    __shared__ bool is_last;
    if (threadIdx.x == 0) {
        g_partials[blockIdx.x] = blocksum;
        __threadfence();                       // make partial visible before count bump
        unsigned int prev = atomicAdd(&g_count, 1u);
        is_last = (prev == gridDim.x - 1);
    }
    __syncthreads();

    if (is_last) {
        // Fixed-order deterministic sum of all block partials.
        float a2 = 0.0f;
        for (int i = threadIdx.x; i < gridDim.x; i += blockDim.x)
            a2 += g_partials[i];

        #pragma unroll
        for (int o = 16; o > 0; o >>= 1)
            a2 += __shfl_down_sync(0xFFFFFFFFu, a2, o);

        if ((threadIdx.x & 31) == 0) s[threadIdx.x >> 5] = a2;
        __syncthreads();

        if (threadIdx.x < 32) {
            float v = (threadIdx.x < (blockDim.x >> 5)) ? s[threadIdx.x] : 0.0f;
            #pragma unroll
            for (int o = 16; o > 0; o >>= 1)
                v += __shfl_down_sync(0xFFFFFFFFu, v, o);
            if (threadIdx.x == 0) {
                out[0] = v * inv_np1;
                g_count = 0;                   // reset for next graph replay
            }
        }
    }
}

extern "C" void kernel_launch(void* const* d_in, const int* in_sizes, int n_in,
                              void* d_out, int out_size) {
    const float4* preds   = (const float4*)d_in[0];
    const float4* targets = (const float4*)d_in[1];
    float* out = (float*)d_out;

    const int n_elems = in_sizes[0];               // N*2 floats
    const int n4      = n_elems >> 2;              // float4 count (2 points each)
    const long long n_points = (long long)n_elems / 2;

    const int THREADS = 256;
    const int BLOCKS  = 1184;                      // 148 SMs * 8 CTAs -> one full wave

    float inv_np1 = 1.0f / (float)(n_points + 1);

    dist_fused_kernel<<<BLOCKS, THREADS>>>(preds, targets, n4, n_elems, inv_np1, out);
}